// round 9
// baseline (speedup 1.0000x reference)
#include <cuda_runtime.h>
#include <cuda_bf16.h>
#include <cuda_fp16.h>
#include <cstdint>
#include <cstddef>

#define BATCH 4
#define MDIM  4096
#define NDIM  4096
#define DQK   256

static constexpr float LOG2E = 1.4426950408889634f;

// ---------------------------------------------------------------------------
// helpers
// ---------------------------------------------------------------------------
__device__ __forceinline__ uint32_t smem_u32(const void* p) {
    uint32_t a;
    asm("{ .reg .u64 t; cvta.to.shared.u64 t, %1; cvt.u32.u64 %0, t; }"
        : "=r"(a) : "l"(p));
    return a;
}

__device__ __forceinline__ float ex2f(float x) {
    float r; asm("ex2.approx.ftz.f32 %0, %1;" : "=f"(r) : "f"(x)); return r;
}

__device__ __forceinline__ void split_pair(float a, float b, uint32_t& hi, uint32_t& lo) {
    __nv_bfloat162 h = __floats2bfloat162_rn(a, b);
    float r0 = a - __bfloat162float(__low2bfloat16(h));
    float r1 = b - __bfloat162float(__high2bfloat16(h));
    __nv_bfloat162 l = __floats2bfloat162_rn(r0, r1);
    hi = *reinterpret_cast<uint32_t*>(&h);
    lo = *reinterpret_cast<uint32_t*>(&l);
}

__device__ __forceinline__ uint32_t pack_h2(float a, float b) {
    __half2 h = __floats2half2_rn(a, b);
    return *reinterpret_cast<uint32_t*>(&h);
}

#define LDSM_X4(r0, r1, r2, r3, a) \
    asm volatile("ldmatrix.sync.aligned.m8n8.x4.shared.b16 {%0,%1,%2,%3}, [%4];" \
                 : "=r"(r0), "=r"(r1), "=r"(r2), "=r"(r3) : "r"(a))

#define LDSM_X4T(r0, r1, r2, r3, a) \
    asm volatile("ldmatrix.sync.aligned.m8n8.x4.trans.shared.b16 {%0,%1,%2,%3}, [%4];" \
                 : "=r"(r0), "=r"(r1), "=r"(r2), "=r"(r3) : "r"(a))

#define MMA_BF16(d, a0, a1, a2, a3, b0, b1)                                    \
    asm volatile("mma.sync.aligned.m16n8k16.row.col.f32.bf16.bf16.f32 "        \
                 "{%0,%1,%2,%3}, {%4,%5,%6,%7}, {%8,%9}, {%0,%1,%2,%3};"       \
                 : "+f"((d)[0]), "+f"((d)[1]), "+f"((d)[2]), "+f"((d)[3])      \
                 : "r"(a0), "r"(a1), "r"(a2), "r"(a3), "r"(b0), "r"(b1))

#define MMA_F16(d, a0, a1, a2, a3, b0, b1)                                     \
    asm volatile("mma.sync.aligned.m16n8k16.row.col.f32.f16.f16.f32 "          \
                 "{%0,%1,%2,%3}, {%4,%5,%6,%7}, {%8,%9}, {%0,%1,%2,%3};"       \
                 : "+f"((d)[0]), "+f"((d)[1]), "+f"((d)[2]), "+f"((d)[3])      \
                 : "r"(a0), "r"(a1), "r"(a2), "r"(a3), "r"(b0), "r"(b1))

#define CP_ASYNC16(dst, src) \
    asm volatile("cp.async.cg.shared.global [%0], [%1], 16;" \
                 :: "r"(dst), "l"(src) : "memory")
#define CP_COMMIT() asm volatile("cp.async.commit_group;" ::: "memory")
#define CP_WAIT1()  asm volatile("cp.async.wait_group 1;" ::: "memory")

// ---------------------------------------------------------------------------
// scratch: fp16 Q(scaled by 0.125*log2e), K, V — row-major [b*4096+row][64]
// ---------------------------------------------------------------------------
__device__ __half g_q[(size_t)BATCH * MDIM * 64];
__device__ __half g_k[(size_t)BATCH * NDIM * 64];
__device__ __half g_v[(size_t)BATCH * NDIM * 64];

// ---------------------------------------------------------------------------
// HMMA projection (bf16 hi/lo 3-MMA internally, fp16 out). Unchanged from R8.
// ---------------------------------------------------------------------------
template <int NC, int MODE>
__device__ __forceinline__ void proj_body(
    char* sm, const float* __restrict__ A, const float* __restrict__ W,
    __half* __restrict__ o0, __half* __restrict__ o1, int bi)
{
    const uint32_t sb = smem_u32(sm);
    constexpr uint32_t OFF_AL = 16384;
    constexpr uint32_t OFF_WH = 32768;
    constexpr uint32_t OFF_WL = 32768 + NC * 128;

    const int t = threadIdx.x, w = t >> 5, lane = t & 31;
    const int mat = lane >> 3, r = lane & 7;
    const int g = lane >> 2, q4 = lane & 3;
    const int r0 = bi * 128;

    float acc[NC / 8][4];
#pragma unroll
    for (int j = 0; j < NC / 8; j++)
#pragma unroll
        for (int i = 0; i < 4; i++) acc[j][i] = 0.f;

    for (int kc = 0; kc < 4; kc++) {
        if (kc) __syncthreads();
#pragma unroll
        for (int i = t; i < 2048; i += 256) {
            int row = i >> 4, c4 = i & 15;
            float4 v = *(const float4*)(A + (size_t)(r0 + row) * DQK + kc * 64 + c4 * 4);
            uint32_t h0, l0, h1, l1;
            split_pair(v.x, v.y, h0, l0);
            split_pair(v.z, v.w, h1, l1);
            uint32_t off = (uint32_t)(row * 128) + (uint32_t)((c4 * 8) ^ ((row & 7) << 4));
            *(uint2*)(sm + off)          = make_uint2(h0, h1);
            *(uint2*)(sm + OFF_AL + off) = make_uint2(l0, l1);
        }
#pragma unroll
        for (int i = t; i < 16 * NC; i += 256) {
            int kr = i / (NC / 4), c4 = i % (NC / 4);
            float4 v = *(const float4*)(W + (size_t)(kc * 64 + kr) * NC + c4 * 4);
            uint32_t h0, l0, h1, l1;
            split_pair(v.x, v.y, h0, l0);
            split_pair(v.z, v.w, h1, l1);
            uint32_t bc = (uint32_t)(c4 * 8);
            uint32_t off = (uint32_t)(kr * NC * 2) + (bc & ~127u)
                         + ((bc & 127u) ^ (uint32_t)((kr & 7) << 4));
            *(uint2*)(sm + OFF_WH + off) = make_uint2(h0, h1);
            *(uint2*)(sm + OFF_WL + off) = make_uint2(l0, l1);
        }
        __syncthreads();

        uint32_t ah[4][4], al[4][4];
#pragma unroll
        for (int kf = 0; kf < 4; kf++) {
            uint32_t off = (uint32_t)((w * 16 + (mat & 1) * 8 + r) * 128)
                         + (uint32_t)((kf * 32 + (mat >> 1) * 16) ^ (r << 4));
            LDSM_X4(ah[kf][0], ah[kf][1], ah[kf][2], ah[kf][3], sb + off);
            LDSM_X4(al[kf][0], al[kf][1], al[kf][2], al[kf][3], sb + OFF_AL + off);
        }

#pragma unroll
        for (int np = 0; np < NC / 16; np++) {
#pragma unroll
            for (int kf = 0; kf < 4; kf++) {
                int krow = kf * 16 + (mat & 1) * 8 + r;
                uint32_t bc = (uint32_t)(np * 32 + (mat >> 1) * 16);
                uint32_t off = (uint32_t)(krow * NC * 2) + (bc & ~127u)
                             + ((bc & 127u) ^ (uint32_t)((krow & 7) << 4));
                uint32_t b0, b1, b2, b3;
                LDSM_X4T(b0, b1, b2, b3, sb + OFF_WH + off);
                MMA_BF16(acc[2 * np],     ah[kf][0], ah[kf][1], ah[kf][2], ah[kf][3], b0, b1);
                MMA_BF16(acc[2 * np + 1], ah[kf][0], ah[kf][1], ah[kf][2], ah[kf][3], b2, b3);
                MMA_BF16(acc[2 * np],     al[kf][0], al[kf][1], al[kf][2], al[kf][3], b0, b1);
                MMA_BF16(acc[2 * np + 1], al[kf][0], al[kf][1], al[kf][2], al[kf][3], b2, b3);
                LDSM_X4T(b0, b1, b2, b3, sb + OFF_WL + off);
                MMA_BF16(acc[2 * np],     ah[kf][0], ah[kf][1], ah[kf][2], ah[kf][3], b0, b1);
                MMA_BF16(acc[2 * np + 1], ah[kf][0], ah[kf][1], ah[kf][2], ah[kf][3], b2, b3);
            }
        }
    }

    const float sc = (MODE == 0) ? 0.125f * LOG2E : 1.f;
    const int row = r0 + w * 16 + g;
#pragma unroll
    for (int j = 0; j < NC / 8; j++) {
        uint32_t p01 = pack_h2(acc[j][0] * sc, acc[j][1] * sc);
        uint32_t p23 = pack_h2(acc[j][2] * sc, acc[j][3] * sc);
        int col = j * 8 + q4 * 2;
        __half* dst = o0;
        int cc = col;
        if (MODE == 1 && col >= 64) { dst = o1; cc = col - 64; }
        *(uint32_t*)(dst + (size_t)row * 64 + cc)       = p01;
        *(uint32_t*)(dst + (size_t)(row + 8) * 64 + cc) = p23;
    }
}

__global__ void __launch_bounds__(256, 2) proj_all(
    const float* __restrict__ x,    const float* __restrict__ Wq,
    const float* __restrict__ cond, const float* __restrict__ Wkv,
    __half* __restrict__ q, __half* __restrict__ k, __half* __restrict__ v)
{
    extern __shared__ char sm[];
    if (blockIdx.x < 128) proj_body<64, 0>(sm, x, Wq, q, nullptr, blockIdx.x);
    else                  proj_body<128, 1>(sm, cond, Wkv, k, v, blockIdx.x - 128);
}

// ---------------------------------------------------------------------------
// Attention (fp16): 1 CTA = 32 q-rows, 4 warps, each warp = 32 rows x 32 keys
// (kw = warp id splits the 128-key tile 4 ways; mt in {0,1} = 16-row halves
// so K/V B-frags are shared across 2 m-tiles). grid 512 -> 3 CTAs/SM.
// 2-stage cp.async ring (stage s at s*32KB: K@+0 16KB, V@+16KB).
// Epilogue: 4-way cross-kw O/l reduction in smem.
// ---------------------------------------------------------------------------
__device__ __forceinline__ void issue_tile(
    uint32_t sb, uint32_t buf, int nt, int t,
    const uint4* k4, const uint4* v4)
{
    const uint4* k = k4 + nt * 1024;
    const uint4* v = v4 + nt * 1024;
#pragma unroll
    for (int i = t; i < 1024; i += 128) {
        int row = i >> 3, c = i & 7;
        uint32_t off = buf + (uint32_t)(row * 128)
                     + (uint32_t)((c * 16) ^ ((row & 7) << 4));
        CP_ASYNC16(sb + off,         k + i);
        CP_ASYNC16(sb + off + 16384, v + i);
    }
}

__global__ void __launch_bounds__(128, 3) attn_kernel(
    const __half* __restrict__ Q, const __half* __restrict__ K,
    const __half* __restrict__ V, float* __restrict__ O)
{
    extern __shared__ char smem[];
    const uint32_t sb = smem_u32(smem);

    const int t    = threadIdx.x;
    const int kw   = t >> 5, lane = t & 31;
    const int g    = lane >> 2, q4 = lane & 3;
    const int mat  = lane >> 3, r = lane & 7;
    const int bb   = blockIdx.y;
    const int m0   = blockIdx.x * 32;

    // ---- stage Q (32 rows, pre-scaled fp16) into stage0, load A-frags ----
    {
        const uint4* q4p = (const uint4*)(Q + ((size_t)(bb * MDIM + m0)) * 64);
#pragma unroll
        for (int i = t; i < 256; i += 128) {
            int row = i >> 3, c = i & 7;
            uint32_t off = (uint32_t)(row * 128) + (uint32_t)((c * 16) ^ ((row & 7) << 4));
            *(uint4*)(smem + off) = q4p[i];
        }
    }
    __syncthreads();

    uint32_t qh[2][4][4];   // mt x kf x 4
#pragma unroll
    for (int mt = 0; mt < 2; mt++)
#pragma unroll
        for (int kf = 0; kf < 4; kf++) {
            uint32_t off = (uint32_t)((mt * 16 + (mat & 1) * 8 + r) * 128)
                         + (uint32_t)((kf * 32 + (mat >> 1) * 16) ^ (r << 4));
            LDSM_X4(qh[mt][kf][0], qh[mt][kf][1], qh[mt][kf][2], qh[mt][kf][3],
                    sb + off);
        }
    __syncthreads();

    float oacc[2][8][4];
#pragma unroll
    for (int mt = 0; mt < 2; mt++)
#pragma unroll
        for (int n = 0; n < 8; n++)
#pragma unroll
            for (int j = 0; j < 4; j++) oacc[mt][n][j] = 0.f;
    float ll[2][2] = {{0.f, 0.f}, {0.f, 0.f}};

    const uint4* k4 = (const uint4*)(K + (size_t)(bb * NDIM) * 64);
    const uint4* v4 = (const uint4*)(V + (size_t)(bb * NDIM) * 64);

    issue_tile(sb, 0,     0, t, k4, v4); CP_COMMIT();
    issue_tile(sb, 32768, 1, t, k4, v4); CP_COMMIT();

    for (int nt = 0; nt < NDIM / 128; ++nt) {
        CP_WAIT1();
        __syncthreads();
        const uint32_t buf = (uint32_t)(nt & 1) * 32768u;

        // this warp's 32 keys = 2 groups of 16
#pragma unroll
        for (int tp = 0; tp < 2; tp++) {
            const int kg = kw * 2 + tp;

            // S: interleaved LDSM -> 4 MMAs per kf (kb live = 4 regs)
            float s[2][2][4];
#pragma unroll
            for (int mt = 0; mt < 2; mt++)
#pragma unroll
                for (int nb = 0; nb < 2; nb++)
#pragma unroll
                    for (int j = 0; j < 4; j++) s[mt][nb][j] = 0.f;

            const uint32_t rowb = (uint32_t)((kg * 16 + (mat >> 1) * 8 + r) * 128);
#pragma unroll
            for (int kf = 0; kf < 4; kf++) {
                uint32_t a = sb + buf + rowb
                           + (uint32_t)((kf * 32 + (mat & 1) * 16) ^ (r << 4));
                uint32_t b0, b1, b2, b3;
                LDSM_X4(b0, b1, b2, b3, a);
                MMA_F16(s[0][0], qh[0][kf][0], qh[0][kf][1], qh[0][kf][2], qh[0][kf][3], b0, b1);
                MMA_F16(s[0][1], qh[0][kf][0], qh[0][kf][1], qh[0][kf][2], qh[0][kf][3], b2, b3);
                MMA_F16(s[1][0], qh[1][kf][0], qh[1][kf][1], qh[1][kf][2], qh[1][kf][3], b0, b1);
                MMA_F16(s[1][1], qh[1][kf][0], qh[1][kf][1], qh[1][kf][2], qh[1][kf][3], b2, b3);
            }

            // exp (Q pre-scaled into exp2 domain), row sums, pack A-frags
            uint32_t pa[2][4];
#pragma unroll
            for (int mt = 0; mt < 2; mt++) {
                float e00 = ex2f(s[mt][0][0]), e01 = ex2f(s[mt][0][1]);
                float e02 = ex2f(s[mt][0][2]), e03 = ex2f(s[mt][0][3]);
                float e10 = ex2f(s[mt][1][0]), e11 = ex2f(s[mt][1][1]);
                float e12 = ex2f(s[mt][1][2]), e13 = ex2f(s[mt][1][3]);
                ll[mt][0] += e00 + e01 + e10 + e11;
                ll[mt][1] += e02 + e03 + e12 + e13;
                pa[mt][0] = pack_h2(e00, e01); pa[mt][1] = pack_h2(e02, e03);
                pa[mt][2] = pack_h2(e10, e11); pa[mt][3] = pack_h2(e12, e13);
            }

            // PV: interleaved LDSM -> 4 MMAs per hp (vb live = 4 regs)
            const uint32_t rowa = (uint32_t)((kg * 16 + (mat & 1) * 8 + r) * 128);
#pragma unroll
            for (int hp = 0; hp < 4; hp++) {
                uint32_t av = sb + buf + 16384 + rowa
                            + (uint32_t)((hp * 32 + (mat >> 1) * 16) ^ (r << 4));
                uint32_t b0, b1, b2, b3;
                LDSM_X4T(b0, b1, b2, b3, av);
                MMA_F16(oacc[0][2 * hp],     pa[0][0], pa[0][1], pa[0][2], pa[0][3], b0, b1);
                MMA_F16(oacc[0][2 * hp + 1], pa[0][0], pa[0][1], pa[0][2], pa[0][3], b2, b3);
                MMA_F16(oacc[1][2 * hp],     pa[1][0], pa[1][1], pa[1][2], pa[1][3], b0, b1);
                MMA_F16(oacc[1][2 * hp + 1], pa[1][0], pa[1][1], pa[1][2], pa[1][3], b2, b3);
            }
        }

        __syncthreads();
        if (nt + 2 < NDIM / 128)
            issue_tile(sb, buf, nt + 2, t, k4, v4);
        CP_COMMIT();
    }

    // ---- epilogue: quad-reduce l; 4-way cross-kw reduction in smem ----
#pragma unroll
    for (int mt = 0; mt < 2; mt++)
#pragma unroll
        for (int h = 0; h < 2; h++) {
            ll[mt][h] += __shfl_xor_sync(0xffffffffu, ll[mt][h], 1);
            ll[mt][h] += __shfl_xor_sync(0xffffffffu, ll[mt][h], 2);
        }

    __syncthreads();
    float* Osm = (float*)smem;             // 3 slabs of [32][64] fp32 = 24KB
    float* lsm = (float*)(smem + 24576);   // 3 slabs of [32] fp32

    if (kw >= 1) {
        float* slab = Osm + (kw - 1) * 2048;
        float* lsl  = lsm + (kw - 1) * 32;
#pragma unroll
        for (int mt = 0; mt < 2; mt++) {
            int rr = mt * 16 + g;
            float* d0 = slab + rr * 64;
            float* d1 = d0 + 8 * 64;
#pragma unroll
            for (int n = 0; n < 8; n++) {
                int col = n * 8 + q4 * 2;
                *(float2*)(d0 + col) = make_float2(oacc[mt][n][0], oacc[mt][n][1]);
                *(float2*)(d1 + col) = make_float2(oacc[mt][n][2], oacc[mt][n][3]);
            }
            if (q4 == 0) {
                lsl[rr]     = ll[mt][0];
                lsl[rr + 8] = ll[mt][1];
            }
        }
    }
    __syncthreads();

    if (kw == 0) {
#pragma unroll
        for (int mt = 0; mt < 2; mt++) {
            int rr = mt * 16 + g;
            const float i0 = 1.f / (ll[mt][0] + lsm[rr] + lsm[32 + rr] + lsm[64 + rr]);
            const float i1 = 1.f / (ll[mt][1] + lsm[rr + 8] + lsm[32 + rr + 8] + lsm[64 + rr + 8]);
            float* Og0 = O + ((size_t)(bb * MDIM + m0 + rr)) * 64;
            float* Og1 = Og0 + 8 * 64;
#pragma unroll
            for (int n = 0; n < 8; n++) {
                int col = n * 8 + q4 * 2;
                float a0x = oacc[mt][n][0], a0y = oacc[mt][n][1];
                float a1x = oacc[mt][n][2], a1y = oacc[mt][n][3];
#pragma unroll
                for (int sl = 0; sl < 3; sl++) {
                    const float* s0 = Osm + sl * 2048 + (mt * 16 + g) * 64;
                    float2 p0 = *(const float2*)(s0 + col);
                    float2 p1 = *(const float2*)(s0 + 8 * 64 + col);
                    a0x += p0.x; a0y += p0.y;
                    a1x += p1.x; a1y += p1.y;
                }
                *(float2*)(Og0 + col) = make_float2(a0x * i0, a0y * i0);
                *(float2*)(Og1 + col) = make_float2(a1x * i1, a1y * i1);
            }
        }
    }
}

// ---------------------------------------------------------------------------
// Launch
// ---------------------------------------------------------------------------
extern "C" void kernel_launch(void* const* d_in, const int* in_sizes, int n_in,
                              void* d_out, int out_size)
{
    const float* x    = (const float*)d_in[0];
    const float* cond = (const float*)d_in[1];
    const float* Wq   = (const float*)d_in[2];
    const float* Wkv  = (const float*)d_in[3];
    float* out = (float*)d_out;

    __half *q, *k, *v;
    cudaGetSymbolAddress((void**)&q, g_q);
    cudaGetSymbolAddress((void**)&k, g_k);
    cudaGetSymbolAddress((void**)&v, g_v);

    cudaFuncSetAttribute(proj_all,
                         cudaFuncAttributeMaxDynamicSharedMemorySize, 65536);
    cudaFuncSetAttribute(attn_kernel,
                         cudaFuncAttributeMaxDynamicSharedMemorySize, 65536);

    proj_all<<<256, 256, 65536>>>(x, Wq, cond, Wkv, q, k, v);

    dim3 grid(MDIM / 32, BATCH);
    attn_kernel<<<grid, 128, 65536>>>(q, k, v, out);
}

// round 10
// speedup vs baseline: 1.2962x; 1.2962x over previous
#include <cuda_runtime.h>
#include <cuda_bf16.h>
#include <cuda_fp16.h>
#include <cstdint>
#include <cstddef>

#define BATCH 4
#define MDIM  4096
#define NDIM  4096
#define DQK   256

static constexpr float LOG2E = 1.4426950408889634f;

// ---------------------------------------------------------------------------
// helpers
// ---------------------------------------------------------------------------
__device__ __forceinline__ uint32_t smem_u32(const void* p) {
    uint32_t a;
    asm("{ .reg .u64 t; cvta.to.shared.u64 t, %1; cvt.u32.u64 %0, t; }"
        : "=r"(a) : "l"(p));
    return a;
}

__device__ __forceinline__ float ex2f(float x) {
    float r; asm("ex2.approx.ftz.f32 %0, %1;" : "=f"(r) : "f"(x)); return r;
}

__device__ __forceinline__ uint32_t pack_h2(float a, float b) {
    __half2 h = __floats2half2_rn(a, b);
    return *reinterpret_cast<uint32_t*>(&h);
}

#define LDSM_X4(r0, r1, r2, r3, a) \
    asm volatile("ldmatrix.sync.aligned.m8n8.x4.shared.b16 {%0,%1,%2,%3}, [%4];" \
                 : "=r"(r0), "=r"(r1), "=r"(r2), "=r"(r3) : "r"(a))

#define LDSM_X4T(r0, r1, r2, r3, a) \
    asm volatile("ldmatrix.sync.aligned.m8n8.x4.trans.shared.b16 {%0,%1,%2,%3}, [%4];" \
                 : "=r"(r0), "=r"(r1), "=r"(r2), "=r"(r3) : "r"(a))

#define MMA_F16(d, a0, a1, a2, a3, b0, b1)                                     \
    asm volatile("mma.sync.aligned.m16n8k16.row.col.f32.f16.f16.f32 "          \
                 "{%0,%1,%2,%3}, {%4,%5,%6,%7}, {%8,%9}, {%0,%1,%2,%3};"       \
                 : "+f"((d)[0]), "+f"((d)[1]), "+f"((d)[2]), "+f"((d)[3])      \
                 : "r"(a0), "r"(a1), "r"(a2), "r"(a3), "r"(b0), "r"(b1))

#define CP_ASYNC16(dst, src) \
    asm volatile("cp.async.cg.shared.global [%0], [%1], 16;" \
                 :: "r"(dst), "l"(src) : "memory")
#define CP_COMMIT() asm volatile("cp.async.commit_group;" ::: "memory")
#define CP_WAIT2()  asm volatile("cp.async.wait_group 2;" ::: "memory")

// ---------------------------------------------------------------------------
// scratch: fp16 Q(scaled by 0.125*log2e), K, V — row-major [b*4096+row][64]
// ---------------------------------------------------------------------------
__device__ __half g_q[(size_t)BATCH * MDIM * 64];
__device__ __half g_k[(size_t)BATCH * NDIM * 64];
__device__ __half g_v[(size_t)BATCH * NDIM * 64];

// ---------------------------------------------------------------------------
// fp16 single-MMA projection: C[128 x NC] = A[128 x 256] @ W[256 x NC].
// A, W converted fp32 -> fp16 on staging (error analysis: q/k/v rel err
// ~2.5e-4 rms, total attn rel err ~4e-4 < 1e-3 threshold).
// MODE 0: scale 0.125*LOG2E at epilogue, all cols -> o0 (Q).
// MODE 1: cols<64 -> o0 (K), else o1 (V).
// smem: Ah@0 (16KB), Wh@16K (NC*64*2 B).
// ---------------------------------------------------------------------------
template <int NC, int MODE>
__device__ __forceinline__ void proj_body(
    char* sm, const float* __restrict__ A, const float* __restrict__ W,
    __half* __restrict__ o0, __half* __restrict__ o1, int bi)
{
    const uint32_t sb = smem_u32(sm);
    constexpr uint32_t OFF_W = 16384;

    const int t = threadIdx.x, w = t >> 5, lane = t & 31;
    const int mat = lane >> 3, r = lane & 7;
    const int g = lane >> 2, q4 = lane & 3;
    const int r0 = bi * 128;

    float acc[NC / 8][4];
#pragma unroll
    for (int j = 0; j < NC / 8; j++)
#pragma unroll
        for (int i = 0; i < 4; i++) acc[j][i] = 0.f;

    for (int kc = 0; kc < 4; kc++) {
        if (kc) __syncthreads();
        // stage A chunk [128 rows x 64 k] fp32 -> fp16 (swizzled 128B rows)
#pragma unroll
        for (int i = t; i < 2048; i += 256) {
            int row = i >> 4, c4 = i & 15;
            float4 v = *(const float4*)(A + (size_t)(r0 + row) * DQK + kc * 64 + c4 * 4);
            uint32_t h0 = pack_h2(v.x, v.y);
            uint32_t h1 = pack_h2(v.z, v.w);
            uint32_t off = (uint32_t)(row * 128) + (uint32_t)((c4 * 8) ^ ((row & 7) << 4));
            *(uint2*)(sm + off) = make_uint2(h0, h1);
        }
        // stage W chunk [64 k x NC] fp32 -> fp16 (blocked 128B atoms)
#pragma unroll
        for (int i = t; i < 16 * NC; i += 256) {
            int kr = i / (NC / 4), c4 = i % (NC / 4);
            float4 v = *(const float4*)(W + (size_t)(kc * 64 + kr) * NC + c4 * 4);
            uint32_t h0 = pack_h2(v.x, v.y);
            uint32_t h1 = pack_h2(v.z, v.w);
            uint32_t bc = (uint32_t)(c4 * 8);
            uint32_t off = (uint32_t)(kr * NC * 2) + (bc & ~127u)
                         + ((bc & 127u) ^ (uint32_t)((kr & 7) << 4));
            *(uint2*)(sm + OFF_W + off) = make_uint2(h0, h1);
        }
        __syncthreads();

        uint32_t ah[4][4];
#pragma unroll
        for (int kf = 0; kf < 4; kf++) {
            uint32_t off = (uint32_t)((w * 16 + (mat & 1) * 8 + r) * 128)
                         + (uint32_t)((kf * 32 + (mat >> 1) * 16) ^ (r << 4));
            LDSM_X4(ah[kf][0], ah[kf][1], ah[kf][2], ah[kf][3], sb + off);
        }

#pragma unroll
        for (int np = 0; np < NC / 16; np++) {
#pragma unroll
            for (int kf = 0; kf < 4; kf++) {
                int krow = kf * 16 + (mat & 1) * 8 + r;
                uint32_t bc = (uint32_t)(np * 32 + (mat >> 1) * 16);
                uint32_t off = (uint32_t)(krow * NC * 2) + (bc & ~127u)
                             + ((bc & 127u) ^ (uint32_t)((krow & 7) << 4));
                uint32_t b0, b1, b2, b3;
                LDSM_X4T(b0, b1, b2, b3, sb + OFF_W + off);
                MMA_F16(acc[2 * np],     ah[kf][0], ah[kf][1], ah[kf][2], ah[kf][3], b0, b1);
                MMA_F16(acc[2 * np + 1], ah[kf][0], ah[kf][1], ah[kf][2], ah[kf][3], b2, b3);
            }
        }
    }

    const float sc = (MODE == 0) ? 0.125f * LOG2E : 1.f;
    const int row = r0 + w * 16 + g;
#pragma unroll
    for (int j = 0; j < NC / 8; j++) {
        uint32_t p01 = pack_h2(acc[j][0] * sc, acc[j][1] * sc);
        uint32_t p23 = pack_h2(acc[j][2] * sc, acc[j][3] * sc);
        int col = j * 8 + q4 * 2;
        __half* dst = o0;
        int cc = col;
        if (MODE == 1 && col >= 64) { dst = o1; cc = col - 64; }
        *(uint32_t*)(dst + (size_t)row * 64 + cc)       = p01;
        *(uint32_t*)(dst + (size_t)(row + 8) * 64 + cc) = p23;
    }
}

__global__ void __launch_bounds__(256, 2) proj_all(
    const float* __restrict__ x,    const float* __restrict__ Wq,
    const float* __restrict__ cond, const float* __restrict__ Wkv,
    __half* __restrict__ q, __half* __restrict__ k, __half* __restrict__ v)
{
    extern __shared__ char sm[];
    if (blockIdx.x < 128) proj_body<64, 0>(sm, x, Wq, q, nullptr, blockIdx.x);
    else                  proj_body<128, 1>(sm, cond, Wkv, k, v, blockIdx.x - 128);
}

// ---------------------------------------------------------------------------
// Attention (fp16): identical to Round-8 best (76.3us config).
// 1 CTA = 64 q-rows, 4 warps 2x2 (mw x kw), 2 CTAs/SM, 3-stage cp.async ring,
// software-pipelined PV one key-group behind S/exp.
// ---------------------------------------------------------------------------
__device__ __forceinline__ void issue_tile(
    uint32_t sb, uint32_t buf, int nt, int t,
    const uint4* k4, const uint4* v4)
{
    const uint4* k = k4 + nt * 1024;
    const uint4* v = v4 + nt * 1024;
#pragma unroll
    for (int i = t; i < 1024; i += 128) {
        int row = i >> 3, c = i & 7;
        uint32_t off = buf + (uint32_t)(row * 128)
                     + (uint32_t)((c * 16) ^ ((row & 7) << 4));
        CP_ASYNC16(sb + off,         k + i);
        CP_ASYNC16(sb + off + 16384, v + i);
    }
}

__global__ void __launch_bounds__(128, 2) attn_kernel(
    const __half* __restrict__ Q, const __half* __restrict__ K,
    const __half* __restrict__ V, float* __restrict__ O)
{
    extern __shared__ char smem[];
    const uint32_t sb = smem_u32(smem);

    const int t    = threadIdx.x;
    const int w    = t >> 5, lane = t & 31;
    const int mw   = w >> 1, kw = w & 1;
    const int g    = lane >> 2, q4 = lane & 3;
    const int mat  = lane >> 3, r = lane & 7;
    const int bb   = blockIdx.y;
    const int m0   = blockIdx.x * 64;

    // ---- stage Q into stage0, load A-frags ----
    {
        const uint4* q4p = (const uint4*)(Q + ((size_t)(bb * MDIM + m0)) * 64);
#pragma unroll
        for (int i = t; i < 512; i += 128) {
            int row = i >> 3, c = i & 7;
            uint32_t off = (uint32_t)(row * 128) + (uint32_t)((c * 16) ^ ((row & 7) << 4));
            *(uint4*)(smem + off) = q4p[i];
        }
    }
    __syncthreads();

    uint32_t qh[2][4][4];
#pragma unroll
    for (int mt = 0; mt < 2; mt++)
#pragma unroll
        for (int kf = 0; kf < 4; kf++) {
            uint32_t off = (uint32_t)((mw * 32 + mt * 16 + (mat & 1) * 8 + r) * 128)
                         + (uint32_t)((kf * 32 + (mat >> 1) * 16) ^ (r << 4));
            LDSM_X4(qh[mt][kf][0], qh[mt][kf][1], qh[mt][kf][2], qh[mt][kf][3],
                    sb + off);
        }
    __syncthreads();

    float oacc[2][8][4];
#pragma unroll
    for (int mt = 0; mt < 2; mt++)
#pragma unroll
        for (int n = 0; n < 8; n++)
#pragma unroll
            for (int j = 0; j < 4; j++) oacc[mt][n][j] = 0.f;
    float ll[2][2] = {{0.f, 0.f}, {0.f, 0.f}};

    const uint4* k4 = (const uint4*)(K + (size_t)(bb * NDIM) * 64);
    const uint4* v4 = (const uint4*)(V + (size_t)(bb * NDIM) * 64);

    issue_tile(sb, 0,     0, t, k4, v4); CP_COMMIT();
    issue_tile(sb, 32768, 1, t, k4, v4); CP_COMMIT();
    issue_tile(sb, 65536, 2, t, k4, v4); CP_COMMIT();

    for (int nt = 0; nt < NDIM / 128; ++nt) {
        CP_WAIT2();
        __syncthreads();
        const uint32_t buf = (uint32_t)(nt % 3) * 32768u;

        uint32_t pa[2][4];    // P frags of previous key group
        uint32_t vb[4][4];    // V frags of previous key group

#pragma unroll
        for (int tp = 0; tp < 5; tp++) {
            if (tp > 0) {
                const int kgp = kw * 4 + tp - 1;
                const uint32_t rowa = (uint32_t)((kgp * 16 + (mat & 1) * 8 + r) * 128);
#pragma unroll
                for (int hp = 0; hp < 4; hp++) {
                    uint32_t av = sb + buf + 16384 + rowa
                                + (uint32_t)((hp * 32 + (mat >> 1) * 16) ^ (r << 4));
                    LDSM_X4T(vb[hp][0], vb[hp][1], vb[hp][2], vb[hp][3], av);
                }
            }

            uint32_t kb[4][4];
            if (tp < 4) {
                const int kg = kw * 4 + tp;
                const uint32_t rowb = (uint32_t)((kg * 16 + (mat >> 1) * 8 + r) * 128);
#pragma unroll
                for (int kf = 0; kf < 4; kf++) {
                    uint32_t a = sb + buf + rowb
                               + (uint32_t)((kf * 32 + (mat & 1) * 16) ^ (r << 4));
                    LDSM_X4(kb[kf][0], kb[kf][1], kb[kf][2], kb[kf][3], a);
                }
            }

            if (tp > 0) {
#pragma unroll
                for (int hp = 0; hp < 4; hp++)
#pragma unroll
                    for (int mt = 0; mt < 2; mt++) {
                        MMA_F16(oacc[mt][2 * hp],     pa[mt][0], pa[mt][1],
                                pa[mt][2], pa[mt][3], vb[hp][0], vb[hp][1]);
                        MMA_F16(oacc[mt][2 * hp + 1], pa[mt][0], pa[mt][1],
                                pa[mt][2], pa[mt][3], vb[hp][2], vb[hp][3]);
                    }
            }

            if (tp < 4) {
                float s[2][2][4];
#pragma unroll
                for (int mt = 0; mt < 2; mt++) {
#pragma unroll
                    for (int nb = 0; nb < 2; nb++)
#pragma unroll
                        for (int j = 0; j < 4; j++) s[mt][nb][j] = 0.f;
#pragma unroll
                    for (int kf = 0; kf < 4; kf++) {
                        MMA_F16(s[mt][0], qh[mt][kf][0], qh[mt][kf][1],
                                qh[mt][kf][2], qh[mt][kf][3], kb[kf][0], kb[kf][1]);
                        MMA_F16(s[mt][1], qh[mt][kf][0], qh[mt][kf][1],
                                qh[mt][kf][2], qh[mt][kf][3], kb[kf][2], kb[kf][3]);
                    }
                }
#pragma unroll
                for (int mt = 0; mt < 2; mt++) {
                    float e00 = ex2f(s[mt][0][0]), e01 = ex2f(s[mt][0][1]);
                    float e02 = ex2f(s[mt][0][2]), e03 = ex2f(s[mt][0][3]);
                    float e10 = ex2f(s[mt][1][0]), e11 = ex2f(s[mt][1][1]);
                    float e12 = ex2f(s[mt][1][2]), e13 = ex2f(s[mt][1][3]);
                    ll[mt][0] += e00 + e01 + e10 + e11;
                    ll[mt][1] += e02 + e03 + e12 + e13;
                    pa[mt][0] = pack_h2(e00, e01); pa[mt][1] = pack_h2(e02, e03);
                    pa[mt][2] = pack_h2(e10, e11); pa[mt][3] = pack_h2(e12, e13);
                }
            }
        }

        __syncthreads();
        if (nt + 3 < NDIM / 128)
            issue_tile(sb, buf, nt + 3, t, k4, v4);
        CP_COMMIT();
    }

    // ---- epilogue: quad-reduce l, cross-kw smem reduction, store ----
#pragma unroll
    for (int mt = 0; mt < 2; mt++)
#pragma unroll
        for (int h = 0; h < 2; h++) {
            ll[mt][h] += __shfl_xor_sync(0xffffffffu, ll[mt][h], 1);
            ll[mt][h] += __shfl_xor_sync(0xffffffffu, ll[mt][h], 2);
        }

    __syncthreads();
    float* Osm = (float*)smem;             // [64 rows][64 cols]
    float* lsm = (float*)(smem + 16384);   // [64 rows]

    if (kw == 1) {
#pragma unroll
        for (int mt = 0; mt < 2; mt++) {
            int rr = mw * 32 + mt * 16 + g;
            float* d0 = Osm + rr * 64;
            float* d1 = d0 + 8 * 64;
#pragma unroll
            for (int n = 0; n < 8; n++) {
                int col = n * 8 + q4 * 2;
                *(float2*)(d0 + col) = make_float2(oacc[mt][n][0], oacc[mt][n][1]);
                *(float2*)(d1 + col) = make_float2(oacc[mt][n][2], oacc[mt][n][3]);
            }
            if (q4 == 0) {
                lsm[rr]     = ll[mt][0];
                lsm[rr + 8] = ll[mt][1];
            }
        }
    }
    __syncthreads();

    if (kw == 0) {
#pragma unroll
        for (int mt = 0; mt < 2; mt++) {
            int rr = mw * 32 + mt * 16 + g;
            const float* s0 = Osm + rr * 64;
            const float* s1 = s0 + 8 * 64;
            const float i0 = 1.f / (ll[mt][0] + lsm[rr]);
            const float i1 = 1.f / (ll[mt][1] + lsm[rr + 8]);
            float* Og0 = O + ((size_t)(bb * MDIM + m0 + rr)) * 64;
            float* Og1 = Og0 + 8 * 64;
#pragma unroll
            for (int n = 0; n < 8; n++) {
                int col = n * 8 + q4 * 2;
                float2 a0 = *(const float2*)(s0 + col);
                float2 a1 = *(const float2*)(s1 + col);
                *(float2*)(Og0 + col) = make_float2((oacc[mt][n][0] + a0.x) * i0,
                                                    (oacc[mt][n][1] + a0.y) * i0);
                *(float2*)(Og1 + col) = make_float2((oacc[mt][n][2] + a1.x) * i1,
                                                    (oacc[mt][n][3] + a1.y) * i1);
            }
        }
    }
}

// ---------------------------------------------------------------------------
// Launch
// ---------------------------------------------------------------------------
extern "C" void kernel_launch(void* const* d_in, const int* in_sizes, int n_in,
                              void* d_out, int out_size)
{
    const float* x    = (const float*)d_in[0];
    const float* cond = (const float*)d_in[1];
    const float* Wq   = (const float*)d_in[2];
    const float* Wkv  = (const float*)d_in[3];
    float* out = (float*)d_out;

    __half *q, *k, *v;
    cudaGetSymbolAddress((void**)&q, g_q);
    cudaGetSymbolAddress((void**)&k, g_k);
    cudaGetSymbolAddress((void**)&v, g_v);

    cudaFuncSetAttribute(proj_all,
                         cudaFuncAttributeMaxDynamicSharedMemorySize, 49152);
    cudaFuncSetAttribute(attn_kernel,
                         cudaFuncAttributeMaxDynamicSharedMemorySize, 98304);

    proj_all<<<256, 256, 49152>>>(x, Wq, cond, Wkv, q, k, v);

    dim3 grid(MDIM / 64, BATCH);
    attn_kernel<<<grid, 128, 98304>>>(q, k, v, out);
}

// round 11
// speedup vs baseline: 1.3343x; 1.0294x over previous
#include <cuda_runtime.h>
#include <cuda_bf16.h>
#include <cuda_fp16.h>
#include <cstdint>
#include <cstddef>

#define BATCH 4
#define MDIM  4096
#define NDIM  4096
#define DQK   256

static constexpr float LOG2E = 1.4426950408889634f;

// ---------------------------------------------------------------------------
// helpers
// ---------------------------------------------------------------------------
__device__ __forceinline__ uint32_t smem_u32(const void* p) {
    uint32_t a;
    asm("{ .reg .u64 t; cvta.to.shared.u64 t, %1; cvt.u32.u64 %0, t; }"
        : "=r"(a) : "l"(p));
    return a;
}

__device__ __forceinline__ float ex2f(float x) {
    float r; asm("ex2.approx.ftz.f32 %0, %1;" : "=f"(r) : "f"(x)); return r;
}

__device__ __forceinline__ uint32_t pack_h2(float a, float b) {
    __half2 h = __floats2half2_rn(a, b);
    return *reinterpret_cast<uint32_t*>(&h);
}

#define LDSM_X4(r0, r1, r2, r3, a) \
    asm volatile("ldmatrix.sync.aligned.m8n8.x4.shared.b16 {%0,%1,%2,%3}, [%4];" \
                 : "=r"(r0), "=r"(r1), "=r"(r2), "=r"(r3) : "r"(a))

#define LDSM_X4T(r0, r1, r2, r3, a) \
    asm volatile("ldmatrix.sync.aligned.m8n8.x4.trans.shared.b16 {%0,%1,%2,%3}, [%4];" \
                 : "=r"(r0), "=r"(r1), "=r"(r2), "=r"(r3) : "r"(a))

#define MMA_F16(d, a0, a1, a2, a3, b0, b1)                                     \
    asm volatile("mma.sync.aligned.m16n8k16.row.col.f32.f16.f16.f32 "          \
                 "{%0,%1,%2,%3}, {%4,%5,%6,%7}, {%8,%9}, {%0,%1,%2,%3};"       \
                 : "+f"((d)[0]), "+f"((d)[1]), "+f"((d)[2]), "+f"((d)[3])      \
                 : "r"(a0), "r"(a1), "r"(a2), "r"(a3), "r"(b0), "r"(b1))

#define CP_ASYNC16(dst, src) \
    asm volatile("cp.async.cg.shared.global [%0], [%1], 16;" \
                 :: "r"(dst), "l"(src) : "memory")
#define CP_COMMIT() asm volatile("cp.async.commit_group;" ::: "memory")
#define CP_WAIT0()  asm volatile("cp.async.wait_group 0;" ::: "memory")
#define CP_WAIT1()  asm volatile("cp.async.wait_group 1;" ::: "memory")
#define CP_WAIT2()  asm volatile("cp.async.wait_group 2;" ::: "memory")

// ---------------------------------------------------------------------------
// scratch: fp16 Q(scaled by 0.125*log2e), K, V — row-major [b*4096+row][64]
// ---------------------------------------------------------------------------
__device__ __half g_q[(size_t)BATCH * MDIM * 64];
__device__ __half g_k[(size_t)BATCH * NDIM * 64];
__device__ __half g_v[(size_t)BATCH * NDIM * 64];

// ---------------------------------------------------------------------------
// fp16 single-MMA projection with cp.async double-buffered A staging.
// C[128 x NC] = A[128 x 256] @ W[256 x NC].
// smem: A16 @0 (16KB, swizzled), W16 @16K (<=16KB), A32 stages @32K (2x32KB).
// MODE 0: scale 0.125*LOG2E at epilogue -> o0 (Q).
// MODE 1: cols<64 -> o0 (K), else o1 (V).
// ---------------------------------------------------------------------------
template <int NC, int MODE>
__device__ __forceinline__ void proj_body(
    char* sm, const float* __restrict__ A, const float* __restrict__ W,
    __half* __restrict__ o0, __half* __restrict__ o1, int bi)
{
    const uint32_t sb = smem_u32(sm);
    constexpr uint32_t OFF_W   = 16384;
    constexpr uint32_t OFF_A32 = 32768;

    const int t = threadIdx.x, w = t >> 5, lane = t & 31;
    const int mat = lane >> 3, r = lane & 7;
    const int g = lane >> 2, q4 = lane & 3;
    const int r0 = bi * 128;

    float acc[NC / 8][4];
#pragma unroll
    for (int j = 0; j < NC / 8; j++)
#pragma unroll
        for (int i = 0; i < 4; i++) acc[j][i] = 0.f;

    // issue cp.async for A chunk kc into fp32 stage (linear layout,
    // element i = (row i>>4, float4 i&15); same mapping used on readback,
    // so wait_group alone makes a thread's own data visible).
    auto issueA = [&](int kc, uint32_t stage) {
        const float* src = A + (size_t)r0 * DQK + kc * 64;
#pragma unroll
        for (int i = t; i < 2048; i += 256) {
            int row = i >> 4, c4 = i & 15;
            CP_ASYNC16(sb + OFF_A32 + stage * 32768u + (uint32_t)i * 16u,
                       src + (size_t)row * DQK + c4 * 4);
        }
    };

    issueA(0, 0); CP_COMMIT();
    issueA(1, 1); CP_COMMIT();

    for (int kc = 0; kc < 4; kc++) {
        if (kc) __syncthreads();   // previous MMA done reading A16/W16

        // ---- W chunk [64 x NC] fp32 -> fp16 (L2-hot, sync load) ----
#pragma unroll
        for (int i = t; i < 16 * NC; i += 256) {
            int kr = i / (NC / 4), c4 = i % (NC / 4);
            float4 v = *(const float4*)(W + (size_t)(kc * 64 + kr) * NC + c4 * 4);
            uint32_t h0 = pack_h2(v.x, v.y);
            uint32_t h1 = pack_h2(v.z, v.w);
            uint32_t bc = (uint32_t)(c4 * 8);
            uint32_t off = (uint32_t)(kr * NC * 2) + (bc & ~127u)
                         + ((bc & 127u) ^ (uint32_t)((kr & 7) << 4));
            *(uint2*)(sm + OFF_W + off) = make_uint2(h0, h1);
        }

        // ---- wait for A stage kc, convert fp32 -> fp16 swizzled ----
        if (kc == 3) { CP_WAIT0(); } else { CP_WAIT1(); }
        const uint32_t stg = OFF_A32 + (uint32_t)(kc & 1) * 32768u;
#pragma unroll
        for (int i = t; i < 2048; i += 256) {
            int row = i >> 4, c4 = i & 15;
            float4 v = *(const float4*)(sm + stg + (uint32_t)i * 16u);
            uint32_t h0 = pack_h2(v.x, v.y);
            uint32_t h1 = pack_h2(v.z, v.w);
            uint32_t off = (uint32_t)(row * 128) + (uint32_t)((c4 * 8) ^ ((row & 7) << 4));
            *(uint2*)(sm + off) = make_uint2(h0, h1);
        }
        __syncthreads();           // A16 + W16 visible to all warps

        // ---- prefetch A chunk kc+2 into the stage just drained ----
        if (kc + 2 < 4) { issueA(kc + 2, (uint32_t)(kc & 1)); }
        CP_COMMIT();

        // ---- MMA for chunk kc ----
        uint32_t ah[4][4];
#pragma unroll
        for (int kf = 0; kf < 4; kf++) {
            uint32_t off = (uint32_t)((w * 16 + (mat & 1) * 8 + r) * 128)
                         + (uint32_t)((kf * 32 + (mat >> 1) * 16) ^ (r << 4));
            LDSM_X4(ah[kf][0], ah[kf][1], ah[kf][2], ah[kf][3], sb + off);
        }
#pragma unroll
        for (int np = 0; np < NC / 16; np++) {
#pragma unroll
            for (int kf = 0; kf < 4; kf++) {
                int krow = kf * 16 + (mat & 1) * 8 + r;
                uint32_t bc = (uint32_t)(np * 32 + (mat >> 1) * 16);
                uint32_t off = (uint32_t)(krow * NC * 2) + (bc & ~127u)
                             + ((bc & 127u) ^ (uint32_t)((krow & 7) << 4));
                uint32_t b0, b1, b2, b3;
                LDSM_X4T(b0, b1, b2, b3, sb + OFF_W + off);
                MMA_F16(acc[2 * np],     ah[kf][0], ah[kf][1], ah[kf][2], ah[kf][3], b0, b1);
                MMA_F16(acc[2 * np + 1], ah[kf][0], ah[kf][1], ah[kf][2], ah[kf][3], b2, b3);
            }
        }
    }

    const float sc = (MODE == 0) ? 0.125f * LOG2E : 1.f;
    const int row = r0 + w * 16 + g;
#pragma unroll
    for (int j = 0; j < NC / 8; j++) {
        uint32_t p01 = pack_h2(acc[j][0] * sc, acc[j][1] * sc);
        uint32_t p23 = pack_h2(acc[j][2] * sc, acc[j][3] * sc);
        int col = j * 8 + q4 * 2;
        __half* dst = o0;
        int cc = col;
        if (MODE == 1 && col >= 64) { dst = o1; cc = col - 64; }
        *(uint32_t*)(dst + (size_t)row * 64 + cc)       = p01;
        *(uint32_t*)(dst + (size_t)(row + 8) * 64 + cc) = p23;
    }
}

__global__ void __launch_bounds__(256, 2) proj_all(
    const float* __restrict__ x,    const float* __restrict__ Wq,
    const float* __restrict__ cond, const float* __restrict__ Wkv,
    __half* __restrict__ q, __half* __restrict__ k, __half* __restrict__ v)
{
    extern __shared__ char sm[];
    if (blockIdx.x < 128) proj_body<128, 1>(sm, cond, Wkv, k, v, blockIdx.x);
    else                  proj_body<64, 0>(sm, x, Wq, q, nullptr, blockIdx.x - 128);
}

// ---------------------------------------------------------------------------
// Attention (fp16): identical to Round-10 (best). 1 CTA = 64 q-rows, 4 warps
// 2x2 (mw x kw), 2 CTAs/SM, 3-stage cp.async ring, PV one key-group behind S.
// ---------------------------------------------------------------------------
__device__ __forceinline__ void issue_tile(
    uint32_t sb, uint32_t buf, int nt, int t,
    const uint4* k4, const uint4* v4)
{
    const uint4* k = k4 + nt * 1024;
    const uint4* v = v4 + nt * 1024;
#pragma unroll
    for (int i = t; i < 1024; i += 128) {
        int row = i >> 3, c = i & 7;
        uint32_t off = buf + (uint32_t)(row * 128)
                     + (uint32_t)((c * 16) ^ ((row & 7) << 4));
        CP_ASYNC16(sb + off,         k + i);
        CP_ASYNC16(sb + off + 16384, v + i);
    }
}

__global__ void __launch_bounds__(128, 2) attn_kernel(
    const __half* __restrict__ Q, const __half* __restrict__ K,
    const __half* __restrict__ V, float* __restrict__ O)
{
    extern __shared__ char smem[];
    const uint32_t sb = smem_u32(smem);

    const int t    = threadIdx.x;
    const int w    = t >> 5, lane = t & 31;
    const int mw   = w >> 1, kw = w & 1;
    const int g    = lane >> 2, q4 = lane & 3;
    const int mat  = lane >> 3, r = lane & 7;
    const int bb   = blockIdx.y;
    const int m0   = blockIdx.x * 64;

    {
        const uint4* q4p = (const uint4*)(Q + ((size_t)(bb * MDIM + m0)) * 64);
#pragma unroll
        for (int i = t; i < 512; i += 128) {
            int row = i >> 3, c = i & 7;
            uint32_t off = (uint32_t)(row * 128) + (uint32_t)((c * 16) ^ ((row & 7) << 4));
            *(uint4*)(smem + off) = q4p[i];
        }
    }
    __syncthreads();

    uint32_t qh[2][4][4];
#pragma unroll
    for (int mt = 0; mt < 2; mt++)
#pragma unroll
        for (int kf = 0; kf < 4; kf++) {
            uint32_t off = (uint32_t)((mw * 32 + mt * 16 + (mat & 1) * 8 + r) * 128)
                         + (uint32_t)((kf * 32 + (mat >> 1) * 16) ^ (r << 4));
            LDSM_X4(qh[mt][kf][0], qh[mt][kf][1], qh[mt][kf][2], qh[mt][kf][3],
                    sb + off);
        }
    __syncthreads();

    float oacc[2][8][4];
#pragma unroll
    for (int mt = 0; mt < 2; mt++)
#pragma unroll
        for (int n = 0; n < 8; n++)
#pragma unroll
            for (int j = 0; j < 4; j++) oacc[mt][n][j] = 0.f;
    float ll[2][2] = {{0.f, 0.f}, {0.f, 0.f}};

    const uint4* k4 = (const uint4*)(K + (size_t)(bb * NDIM) * 64);
    const uint4* v4 = (const uint4*)(V + (size_t)(bb * NDIM) * 64);

    issue_tile(sb, 0,     0, t, k4, v4); CP_COMMIT();
    issue_tile(sb, 32768, 1, t, k4, v4); CP_COMMIT();
    issue_tile(sb, 65536, 2, t, k4, v4); CP_COMMIT();

    for (int nt = 0; nt < NDIM / 128; ++nt) {
        CP_WAIT2();
        __syncthreads();
        const uint32_t buf = (uint32_t)(nt % 3) * 32768u;

        uint32_t pa[2][4];
        uint32_t vb[4][4];

#pragma unroll
        for (int tp = 0; tp < 5; tp++) {
            if (tp > 0) {
                const int kgp = kw * 4 + tp - 1;
                const uint32_t rowa = (uint32_t)((kgp * 16 + (mat & 1) * 8 + r) * 128);
#pragma unroll
                for (int hp = 0; hp < 4; hp++) {
                    uint32_t av = sb + buf + 16384 + rowa
                                + (uint32_t)((hp * 32 + (mat >> 1) * 16) ^ (r << 4));
                    LDSM_X4T(vb[hp][0], vb[hp][1], vb[hp][2], vb[hp][3], av);
                }
            }

            uint32_t kb[4][4];
            if (tp < 4) {
                const int kg = kw * 4 + tp;
                const uint32_t rowb = (uint32_t)((kg * 16 + (mat >> 1) * 8 + r) * 128);
#pragma unroll
                for (int kf = 0; kf < 4; kf++) {
                    uint32_t a = sb + buf + rowb
                               + (uint32_t)((kf * 32 + (mat & 1) * 16) ^ (r << 4));
                    LDSM_X4(kb[kf][0], kb[kf][1], kb[kf][2], kb[kf][3], a);
                }
            }

            if (tp > 0) {
#pragma unroll
                for (int hp = 0; hp < 4; hp++)
#pragma unroll
                    for (int mt = 0; mt < 2; mt++) {
                        MMA_F16(oacc[mt][2 * hp],     pa[mt][0], pa[mt][1],
                                pa[mt][2], pa[mt][3], vb[hp][0], vb[hp][1]);
                        MMA_F16(oacc[mt][2 * hp + 1], pa[mt][0], pa[mt][1],
                                pa[mt][2], pa[mt][3], vb[hp][2], vb[hp][3]);
                    }
            }

            if (tp < 4) {
                float s[2][2][4];
#pragma unroll
                for (int mt = 0; mt < 2; mt++) {
#pragma unroll
                    for (int nb = 0; nb < 2; nb++)
#pragma unroll
                        for (int j = 0; j < 4; j++) s[mt][nb][j] = 0.f;
#pragma unroll
                    for (int kf = 0; kf < 4; kf++) {
                        MMA_F16(s[mt][0], qh[mt][kf][0], qh[mt][kf][1],
                                qh[mt][kf][2], qh[mt][kf][3], kb[kf][0], kb[kf][1]);
                        MMA_F16(s[mt][1], qh[mt][kf][0], qh[mt][kf][1],
                                qh[mt][kf][2], qh[mt][kf][3], kb[kf][2], kb[kf][3]);
                    }
                }
#pragma unroll
                for (int mt = 0; mt < 2; mt++) {
                    float e00 = ex2f(s[mt][0][0]), e01 = ex2f(s[mt][0][1]);
                    float e02 = ex2f(s[mt][0][2]), e03 = ex2f(s[mt][0][3]);
                    float e10 = ex2f(s[mt][1][0]), e11 = ex2f(s[mt][1][1]);
                    float e12 = ex2f(s[mt][1][2]), e13 = ex2f(s[mt][1][3]);
                    ll[mt][0] += e00 + e01 + e10 + e11;
                    ll[mt][1] += e02 + e03 + e12 + e13;
                    pa[mt][0] = pack_h2(e00, e01); pa[mt][1] = pack_h2(e02, e03);
                    pa[mt][2] = pack_h2(e10, e11); pa[mt][3] = pack_h2(e12, e13);
                }
            }
        }

        __syncthreads();
        if (nt + 3 < NDIM / 128)
            issue_tile(sb, buf, nt + 3, t, k4, v4);
        CP_COMMIT();
    }

#pragma unroll
    for (int mt = 0; mt < 2; mt++)
#pragma unroll
        for (int h = 0; h < 2; h++) {
            ll[mt][h] += __shfl_xor_sync(0xffffffffu, ll[mt][h], 1);
            ll[mt][h] += __shfl_xor_sync(0xffffffffu, ll[mt][h], 2);
        }

    __syncthreads();
    float* Osm = (float*)smem;             // [64 rows][64 cols]
    float* lsm = (float*)(smem + 16384);   // [64 rows]

    if (kw == 1) {
#pragma unroll
        for (int mt = 0; mt < 2; mt++) {
            int rr = mw * 32 + mt * 16 + g;
            float* d0 = Osm + rr * 64;
            float* d1 = d0 + 8 * 64;
#pragma unroll
            for (int n = 0; n < 8; n++) {
                int col = n * 8 + q4 * 2;
                *(float2*)(d0 + col) = make_float2(oacc[mt][n][0], oacc[mt][n][1]);
                *(float2*)(d1 + col) = make_float2(oacc[mt][n][2], oacc[mt][n][3]);
            }
            if (q4 == 0) {
                lsm[rr]     = ll[mt][0];
                lsm[rr + 8] = ll[mt][1];
            }
        }
    }
    __syncthreads();

    if (kw == 0) {
#pragma unroll
        for (int mt = 0; mt < 2; mt++) {
            int rr = mw * 32 + mt * 16 + g;
            const float* s0 = Osm + rr * 64;
            const float* s1 = s0 + 8 * 64;
            const float i0 = 1.f / (ll[mt][0] + lsm[rr]);
            const float i1 = 1.f / (ll[mt][1] + lsm[rr + 8]);
            float* Og0 = O + ((size_t)(bb * MDIM + m0 + rr)) * 64;
            float* Og1 = Og0 + 8 * 64;
#pragma unroll
            for (int n = 0; n < 8; n++) {
                int col = n * 8 + q4 * 2;
                float2 a0 = *(const float2*)(s0 + col);
                float2 a1 = *(const float2*)(s1 + col);
                *(float2*)(Og0 + col) = make_float2((oacc[mt][n][0] + a0.x) * i0,
                                                    (oacc[mt][n][1] + a0.y) * i0);
                *(float2*)(Og1 + col) = make_float2((oacc[mt][n][2] + a1.x) * i1,
                                                    (oacc[mt][n][3] + a1.y) * i1);
            }
        }
    }
}

// ---------------------------------------------------------------------------
// Launch
// ---------------------------------------------------------------------------
extern "C" void kernel_launch(void* const* d_in, const int* in_sizes, int n_in,
                              void* d_out, int out_size)
{
    const float* x    = (const float*)d_in[0];
    const float* cond = (const float*)d_in[1];
    const float* Wq   = (const float*)d_in[2];
    const float* Wkv  = (const float*)d_in[3];
    float* out = (float*)d_out;

    __half *q, *k, *v;
    cudaGetSymbolAddress((void**)&q, g_q);
    cudaGetSymbolAddress((void**)&k, g_k);
    cudaGetSymbolAddress((void**)&v, g_v);

    cudaFuncSetAttribute(proj_all,
                         cudaFuncAttributeMaxDynamicSharedMemorySize, 98304);
    cudaFuncSetAttribute(attn_kernel,
                         cudaFuncAttributeMaxDynamicSharedMemorySize, 98304);

    proj_all<<<256, 256, 98304>>>(x, Wq, cond, Wkv, q, k, v);

    dim3 grid(MDIM / 64, BATCH);
    attn_kernel<<<grid, 128, 98304>>>(q, k, v, out);
}

// round 12
// speedup vs baseline: 1.3401x; 1.0044x over previous
#include <cuda_runtime.h>
#include <cuda_bf16.h>
#include <cuda_fp16.h>
#include <cstdint>
#include <cstddef>

#define BATCH 4
#define MDIM  4096
#define NDIM  4096
#define DQK   256

static constexpr float LOG2E = 1.4426950408889634f;

// ---------------------------------------------------------------------------
// helpers
// ---------------------------------------------------------------------------
__device__ __forceinline__ uint32_t smem_u32(const void* p) {
    uint32_t a;
    asm("{ .reg .u64 t; cvta.to.shared.u64 t, %1; cvt.u32.u64 %0, t; }"
        : "=r"(a) : "l"(p));
    return a;
}

__device__ __forceinline__ float ex2f(float x) {
    float r; asm("ex2.approx.ftz.f32 %0, %1;" : "=f"(r) : "f"(x)); return r;
}

__device__ __forceinline__ uint32_t pack_h2(float a, float b) {
    __half2 h = __floats2half2_rn(a, b);
    return *reinterpret_cast<uint32_t*>(&h);
}

#define LDSM_X4(r0, r1, r2, r3, a) \
    asm volatile("ldmatrix.sync.aligned.m8n8.x4.shared.b16 {%0,%1,%2,%3}, [%4];" \
                 : "=r"(r0), "=r"(r1), "=r"(r2), "=r"(r3) : "r"(a))

#define LDSM_X4T(r0, r1, r2, r3, a) \
    asm volatile("ldmatrix.sync.aligned.m8n8.x4.trans.shared.b16 {%0,%1,%2,%3}, [%4];" \
                 : "=r"(r0), "=r"(r1), "=r"(r2), "=r"(r3) : "r"(a))

#define MMA_F16(d, a0, a1, a2, a3, b0, b1)                                     \
    asm volatile("mma.sync.aligned.m16n8k16.row.col.f32.f16.f16.f32 "          \
                 "{%0,%1,%2,%3}, {%4,%5,%6,%7}, {%8,%9}, {%0,%1,%2,%3};"       \
                 : "+f"((d)[0]), "+f"((d)[1]), "+f"((d)[2]), "+f"((d)[3])      \
                 : "r"(a0), "r"(a1), "r"(a2), "r"(a3), "r"(b0), "r"(b1))

#define CP_ASYNC16(dst, src) \
    asm volatile("cp.async.cg.shared.global [%0], [%1], 16;" \
                 :: "r"(dst), "l"(src) : "memory")
#define CP_COMMIT() asm volatile("cp.async.commit_group;" ::: "memory")
#define CP_WAIT0()  asm volatile("cp.async.wait_group 0;" ::: "memory")
#define CP_WAIT1()  asm volatile("cp.async.wait_group 1;" ::: "memory")
#define CP_WAIT2()  asm volatile("cp.async.wait_group 2;" ::: "memory")

// ---------------------------------------------------------------------------
// scratch: fp16 K, V — row-major [b*4096+n][64]
// ---------------------------------------------------------------------------
__device__ __half g_k[(size_t)BATCH * NDIM * 64];
__device__ __half g_v[(size_t)BATCH * NDIM * 64];

// ---------------------------------------------------------------------------
// KV projection: 64 rows/CTA, 128 threads (4 warps x 16 rows), grid 256.
// kv[64 x 128] = cond[64 x 256] @ Wkv[256 x 128]; cols<64 -> K, else V.
// cp.async double-buffered A staging.
// smem: A16 @0 (8KB), W16 @8K (16KB), A32 stages @24K (2 x 16KB) = 56KB.
// ---------------------------------------------------------------------------
__global__ void __launch_bounds__(128, 2) kv_proj(
    const float* __restrict__ A, const float* __restrict__ W,
    __half* __restrict__ ko, __half* __restrict__ vo)
{
    extern __shared__ char sm[];
    const uint32_t sb = smem_u32(sm);
    constexpr uint32_t OFF_W   = 8192;
    constexpr uint32_t OFF_A32 = 24576;

    const int t = threadIdx.x, w = t >> 5, lane = t & 31;
    const int mat = lane >> 3, r = lane & 7;
    const int g = lane >> 2, q4 = lane & 3;
    const int r0 = blockIdx.x * 64;

    float acc[16][4];
#pragma unroll
    for (int j = 0; j < 16; j++)
#pragma unroll
        for (int i = 0; i < 4; i++) acc[j][i] = 0.f;

    auto issueA = [&](int kc, uint32_t stage) {
        const float* src = A + (size_t)r0 * DQK + kc * 64;
#pragma unroll
        for (int i = t; i < 1024; i += 128) {
            int row = i >> 4, c4 = i & 15;
            CP_ASYNC16(sb + OFF_A32 + stage * 16384u + (uint32_t)i * 16u,
                       src + (size_t)row * DQK + c4 * 4);
        }
    };

    issueA(0, 0); CP_COMMIT();
    issueA(1, 1); CP_COMMIT();

    for (int kc = 0; kc < 4; kc++) {
        if (kc) __syncthreads();

        // W chunk [64 x 128] fp32 -> fp16
#pragma unroll
        for (int i = t; i < 2048; i += 128) {
            int kr = i >> 5, c4 = i & 31;
            float4 v = *(const float4*)(W + (size_t)(kc * 64 + kr) * 128 + c4 * 4);
            uint32_t h0 = pack_h2(v.x, v.y);
            uint32_t h1 = pack_h2(v.z, v.w);
            uint32_t bc = (uint32_t)(c4 * 8);
            uint32_t off = (uint32_t)(kr * 256) + (bc & ~127u)
                         + ((bc & 127u) ^ (uint32_t)((kr & 7) << 4));
            *(uint2*)(sm + OFF_W + off) = make_uint2(h0, h1);
        }

        if (kc == 3) { CP_WAIT0(); } else { CP_WAIT1(); }
        const uint32_t stg = OFF_A32 + (uint32_t)(kc & 1) * 16384u;
#pragma unroll
        for (int i = t; i < 1024; i += 128) {
            int row = i >> 4, c4 = i & 15;
            float4 v = *(const float4*)(sm + stg + (uint32_t)i * 16u);
            uint32_t h0 = pack_h2(v.x, v.y);
            uint32_t h1 = pack_h2(v.z, v.w);
            uint32_t off = (uint32_t)(row * 128) + (uint32_t)((c4 * 8) ^ ((row & 7) << 4));
            *(uint2*)(sm + off) = make_uint2(h0, h1);
        }
        __syncthreads();

        if (kc + 2 < 4) { issueA(kc + 2, (uint32_t)(kc & 1)); }
        CP_COMMIT();

        uint32_t ah[4][4];
#pragma unroll
        for (int kf = 0; kf < 4; kf++) {
            uint32_t off = (uint32_t)((w * 16 + (mat & 1) * 8 + r) * 128)
                         + (uint32_t)((kf * 32 + (mat >> 1) * 16) ^ (r << 4));
            LDSM_X4(ah[kf][0], ah[kf][1], ah[kf][2], ah[kf][3], sb + off);
        }
#pragma unroll
        for (int np = 0; np < 8; np++) {
#pragma unroll
            for (int kf = 0; kf < 4; kf++) {
                int krow = kf * 16 + (mat & 1) * 8 + r;
                uint32_t bc = (uint32_t)(np * 32 + (mat >> 1) * 16);
                uint32_t off = (uint32_t)(krow * 256) + (bc & ~127u)
                             + ((bc & 127u) ^ (uint32_t)((krow & 7) << 4));
                uint32_t b0, b1, b2, b3;
                LDSM_X4T(b0, b1, b2, b3, sb + OFF_W + off);
                MMA_F16(acc[2 * np],     ah[kf][0], ah[kf][1], ah[kf][2], ah[kf][3], b0, b1);
                MMA_F16(acc[2 * np + 1], ah[kf][0], ah[kf][1], ah[kf][2], ah[kf][3], b2, b3);
            }
        }
    }

    const int row = r0 + w * 16 + g;
#pragma unroll
    for (int j = 0; j < 16; j++) {
        uint32_t p01 = pack_h2(acc[j][0], acc[j][1]);
        uint32_t p23 = pack_h2(acc[j][2], acc[j][3]);
        int col = j * 8 + q4 * 2;
        __half* dst = (col < 64) ? ko : vo;
        int cc = (col < 64) ? col : col - 64;
        *(uint32_t*)(dst + (size_t)row * 64 + cc)       = p01;
        *(uint32_t*)(dst + (size_t)(row + 8) * 64 + cc) = p23;
    }
}

// ---------------------------------------------------------------------------
// Attention (fp16) with FUSED Q projection prologue.
// 1 CTA = 64 q-rows, 4 warps 2x2 (mw x kw), 2 CTAs/SM, 3-stage cp.async ring,
// PV one key-group behind S. qh A-frags computed in-register from
// x @ Wq via C-frag -> A-frag packing (scale 0.125*log2e folded at pack).
// Prologue smem: x16 chunk @0 (8KB), Wq16 @32768 (32KB) — inside ring area,
// fully consumed before ring prefetch starts.
// ---------------------------------------------------------------------------
__device__ __forceinline__ void issue_tile(
    uint32_t sb, uint32_t buf, int nt, int t,
    const uint4* k4, const uint4* v4)
{
    const uint4* k = k4 + nt * 1024;
    const uint4* v = v4 + nt * 1024;
#pragma unroll
    for (int i = t; i < 1024; i += 128) {
        int row = i >> 3, c = i & 7;
        uint32_t off = buf + (uint32_t)(row * 128)
                     + (uint32_t)((c * 16) ^ ((row & 7) << 4));
        CP_ASYNC16(sb + off,         k + i);
        CP_ASYNC16(sb + off + 16384, v + i);
    }
}

__global__ void __launch_bounds__(128, 2) attn_kernel(
    const float* __restrict__ X, const float* __restrict__ Wq,
    const __half* __restrict__ K, const __half* __restrict__ V,
    float* __restrict__ O)
{
    extern __shared__ char smem[];
    const uint32_t sb = smem_u32(smem);

    const int t    = threadIdx.x;
    const int w    = t >> 5, lane = t & 31;
    const int mw   = w >> 1, kw = w & 1;
    const int g    = lane >> 2, q4 = lane & 3;
    const int mat  = lane >> 3, r = lane & 7;
    const int bb   = blockIdx.y;
    const int m0   = blockIdx.x * 64;

    // ================= Q-projection prologue =================
    uint32_t qh[2][4][4];
    {
        constexpr uint32_t OFF_WQ = 32768;
        // stage Wq [256 x 64] fp32 -> fp16 (L2-broadcast across CTAs)
#pragma unroll
        for (int i = t; i < 4096; i += 128) {
            int kr = i >> 4, c4 = i & 15;
            float4 v = *(const float4*)(Wq + (size_t)kr * 64 + c4 * 4);
            uint32_t h0 = pack_h2(v.x, v.y);
            uint32_t h1 = pack_h2(v.z, v.w);
            uint32_t bc = (uint32_t)(c4 * 8);
            uint32_t off = (uint32_t)(kr * 128) + (bc ^ (uint32_t)((kr & 7) << 4));
            *(uint2*)(smem + OFF_WQ + off) = make_uint2(h0, h1);
        }

        float qacc[2][8][4];
#pragma unroll
        for (int mt = 0; mt < 2; mt++)
#pragma unroll
            for (int j = 0; j < 8; j++)
#pragma unroll
                for (int i = 0; i < 4; i++) qacc[mt][j][i] = 0.f;

        const float* Xb = X + (size_t)(bb * MDIM + m0) * DQK;
        for (int kc = 0; kc < 4; kc++) {
            __syncthreads();   // previous chunk's x16 reads done (and Wq staged)
            // stage x chunk [64 rows x 64 k] fp32 -> fp16 @0
#pragma unroll
            for (int i = t; i < 1024; i += 128) {
                int row = i >> 4, c4 = i & 15;
                float4 v = *(const float4*)(Xb + (size_t)row * DQK + kc * 64 + c4 * 4);
                uint32_t h0 = pack_h2(v.x, v.y);
                uint32_t h1 = pack_h2(v.z, v.w);
                uint32_t off = (uint32_t)(row * 128)
                             + (uint32_t)((c4 * 8) ^ ((row & 7) << 4));
                *(uint2*)(smem + off) = make_uint2(h0, h1);
            }
            __syncthreads();

            uint32_t ax[2][4][4];
#pragma unroll
            for (int mt = 0; mt < 2; mt++)
#pragma unroll
                for (int kf = 0; kf < 4; kf++) {
                    uint32_t off = (uint32_t)((mw * 32 + mt * 16 + (mat & 1) * 8 + r) * 128)
                                 + (uint32_t)((kf * 32 + (mat >> 1) * 16) ^ (r << 4));
                    LDSM_X4(ax[mt][kf][0], ax[mt][kf][1], ax[mt][kf][2], ax[mt][kf][3],
                            sb + off);
                }
#pragma unroll
            for (int np = 0; np < 4; np++) {
#pragma unroll
                for (int kf = 0; kf < 4; kf++) {
                    int krow = kc * 64 + kf * 16 + (mat & 1) * 8 + r;
                    uint32_t bc = (uint32_t)(np * 32 + (mat >> 1) * 16);
                    uint32_t off = (uint32_t)(krow * 128)
                                 + (bc ^ (uint32_t)((krow & 7) << 4));
                    uint32_t b0, b1, b2, b3;
                    LDSM_X4T(b0, b1, b2, b3, sb + OFF_WQ + off);
#pragma unroll
                    for (int mt = 0; mt < 2; mt++) {
                        MMA_F16(qacc[mt][2 * np],     ax[mt][kf][0], ax[mt][kf][1],
                                ax[mt][kf][2], ax[mt][kf][3], b0, b1);
                        MMA_F16(qacc[mt][2 * np + 1], ax[mt][kf][0], ax[mt][kf][1],
                                ax[mt][kf][2], ax[mt][kf][3], b2, b3);
                    }
                }
            }
        }

        // C-frag -> A-frag pack with scale
        const float sc = 0.125f * LOG2E;
#pragma unroll
        for (int mt = 0; mt < 2; mt++)
#pragma unroll
            for (int kf = 0; kf < 4; kf++) {
                qh[mt][kf][0] = pack_h2(qacc[mt][2*kf][0] * sc,   qacc[mt][2*kf][1] * sc);
                qh[mt][kf][1] = pack_h2(qacc[mt][2*kf][2] * sc,   qacc[mt][2*kf][3] * sc);
                qh[mt][kf][2] = pack_h2(qacc[mt][2*kf+1][0] * sc, qacc[mt][2*kf+1][1] * sc);
                qh[mt][kf][3] = pack_h2(qacc[mt][2*kf+1][2] * sc, qacc[mt][2*kf+1][3] * sc);
            }
        __syncthreads();   // prologue smem fully consumed
    }
    // ================= end prologue =================

    float oacc[2][8][4];
#pragma unroll
    for (int mt = 0; mt < 2; mt++)
#pragma unroll
        for (int n = 0; n < 8; n++)
#pragma unroll
            for (int j = 0; j < 4; j++) oacc[mt][n][j] = 0.f;
    float ll[2][2] = {{0.f, 0.f}, {0.f, 0.f}};

    const uint4* k4 = (const uint4*)(K + (size_t)(bb * NDIM) * 64);
    const uint4* v4 = (const uint4*)(V + (size_t)(bb * NDIM) * 64);

    issue_tile(sb, 0,     0, t, k4, v4); CP_COMMIT();
    issue_tile(sb, 32768, 1, t, k4, v4); CP_COMMIT();
    issue_tile(sb, 65536, 2, t, k4, v4); CP_COMMIT();

    for (int nt = 0; nt < NDIM / 128; ++nt) {
        CP_WAIT2();
        __syncthreads();
        const uint32_t buf = (uint32_t)(nt % 3) * 32768u;

        uint32_t pa[2][4];
        uint32_t vb[4][4];

#pragma unroll
        for (int tp = 0; tp < 5; tp++) {
            if (tp > 0) {
                const int kgp = kw * 4 + tp - 1;
                const uint32_t rowa = (uint32_t)((kgp * 16 + (mat & 1) * 8 + r) * 128);
#pragma unroll
                for (int hp = 0; hp < 4; hp++) {
                    uint32_t av = sb + buf + 16384 + rowa
                                + (uint32_t)((hp * 32 + (mat >> 1) * 16) ^ (r << 4));
                    LDSM_X4T(vb[hp][0], vb[hp][1], vb[hp][2], vb[hp][3], av);
                }
            }

            uint32_t kb[4][4];
            if (tp < 4) {
                const int kg = kw * 4 + tp;
                const uint32_t rowb = (uint32_t)((kg * 16 + (mat >> 1) * 8 + r) * 128);
#pragma unroll
                for (int kf = 0; kf < 4; kf++) {
                    uint32_t a = sb + buf + rowb
                               + (uint32_t)((kf * 32 + (mat & 1) * 16) ^ (r << 4));
                    LDSM_X4(kb[kf][0], kb[kf][1], kb[kf][2], kb[kf][3], a);
                }
            }

            if (tp > 0) {
#pragma unroll
                for (int hp = 0; hp < 4; hp++)
#pragma unroll
                    for (int mt = 0; mt < 2; mt++) {
                        MMA_F16(oacc[mt][2 * hp],     pa[mt][0], pa[mt][1],
                                pa[mt][2], pa[mt][3], vb[hp][0], vb[hp][1]);
                        MMA_F16(oacc[mt][2 * hp + 1], pa[mt][0], pa[mt][1],
                                pa[mt][2], pa[mt][3], vb[hp][2], vb[hp][3]);
                    }
            }

            if (tp < 4) {
                float s[2][2][4];
#pragma unroll
                for (int mt = 0; mt < 2; mt++) {
#pragma unroll
                    for (int nb = 0; nb < 2; nb++)
#pragma unroll
                        for (int j = 0; j < 4; j++) s[mt][nb][j] = 0.f;
#pragma unroll
                    for (int kf = 0; kf < 4; kf++) {
                        MMA_F16(s[mt][0], qh[mt][kf][0], qh[mt][kf][1],
                                qh[mt][kf][2], qh[mt][kf][3], kb[kf][0], kb[kf][1]);
                        MMA_F16(s[mt][1], qh[mt][kf][0], qh[mt][kf][1],
                                qh[mt][kf][2], qh[mt][kf][3], kb[kf][2], kb[kf][3]);
                    }
                }
#pragma unroll
                for (int mt = 0; mt < 2; mt++) {
                    float e00 = ex2f(s[mt][0][0]), e01 = ex2f(s[mt][0][1]);
                    float e02 = ex2f(s[mt][0][2]), e03 = ex2f(s[mt][0][3]);
                    float e10 = ex2f(s[mt][1][0]), e11 = ex2f(s[mt][1][1]);
                    float e12 = ex2f(s[mt][1][2]), e13 = ex2f(s[mt][1][3]);
                    ll[mt][0] += e00 + e01 + e10 + e11;
                    ll[mt][1] += e02 + e03 + e12 + e13;
                    pa[mt][0] = pack_h2(e00, e01); pa[mt][1] = pack_h2(e02, e03);
                    pa[mt][2] = pack_h2(e10, e11); pa[mt][3] = pack_h2(e12, e13);
                }
            }
        }

        __syncthreads();
        if (nt + 3 < NDIM / 128)
            issue_tile(sb, buf, nt + 3, t, k4, v4);
        CP_COMMIT();
    }

#pragma unroll
    for (int mt = 0; mt < 2; mt++)
#pragma unroll
        for (int h = 0; h < 2; h++) {
            ll[mt][h] += __shfl_xor_sync(0xffffffffu, ll[mt][h], 1);
            ll[mt][h] += __shfl_xor_sync(0xffffffffu, ll[mt][h], 2);
        }

    __syncthreads();
    float* Osm = (float*)smem;             // [64 rows][64 cols]
    float* lsm = (float*)(smem + 16384);   // [64 rows]

    if (kw == 1) {
#pragma unroll
        for (int mt = 0; mt < 2; mt++) {
            int rr = mw * 32 + mt * 16 + g;
            float* d0 = Osm + rr * 64;
            float* d1 = d0 + 8 * 64;
#pragma unroll
            for (int n = 0; n < 8; n++) {
                int col = n * 8 + q4 * 2;
                *(float2*)(d0 + col) = make_float2(oacc[mt][n][0], oacc[mt][n][1]);
                *(float2*)(d1 + col) = make_float2(oacc[mt][n][2], oacc[mt][n][3]);
            }
            if (q4 == 0) {
                lsm[rr]     = ll[mt][0];
                lsm[rr + 8] = ll[mt][1];
            }
        }
    }
    __syncthreads();

    if (kw == 0) {
#pragma unroll
        for (int mt = 0; mt < 2; mt++) {
            int rr = mw * 32 + mt * 16 + g;
            const float* s0 = Osm + rr * 64;
            const float* s1 = s0 + 8 * 64;
            const float i0 = 1.f / (ll[mt][0] + lsm[rr]);
            const float i1 = 1.f / (ll[mt][1] + lsm[rr + 8]);
            float* Og0 = O + ((size_t)(bb * MDIM + m0 + rr)) * 64;
            float* Og1 = Og0 + 8 * 64;
#pragma unroll
            for (int n = 0; n < 8; n++) {
                int col = n * 8 + q4 * 2;
                float2 a0 = *(const float2*)(s0 + col);
                float2 a1 = *(const float2*)(s1 + col);
                *(float2*)(Og0 + col) = make_float2((oacc[mt][n][0] + a0.x) * i0,
                                                    (oacc[mt][n][1] + a0.y) * i0);
                *(float2*)(Og1 + col) = make_float2((oacc[mt][n][2] + a1.x) * i1,
                                                    (oacc[mt][n][3] + a1.y) * i1);
            }
        }
    }
}

// ---------------------------------------------------------------------------
// Launch
// ---------------------------------------------------------------------------
extern "C" void kernel_launch(void* const* d_in, const int* in_sizes, int n_in,
                              void* d_out, int out_size)
{
    const float* x    = (const float*)d_in[0];
    const float* cond = (const float*)d_in[1];
    const float* Wq   = (const float*)d_in[2];
    const float* Wkv  = (const float*)d_in[3];
    float* out = (float*)d_out;

    __half *k, *v;
    cudaGetSymbolAddress((void**)&k, g_k);
    cudaGetSymbolAddress((void**)&v, g_v);

    cudaFuncSetAttribute(kv_proj,
                         cudaFuncAttributeMaxDynamicSharedMemorySize, 57344);
    cudaFuncSetAttribute(attn_kernel,
                         cudaFuncAttributeMaxDynamicSharedMemorySize, 98304);

    kv_proj<<<BATCH * NDIM / 64, 128, 57344>>>(cond, Wkv, k, v);

    dim3 grid(MDIM / 64, BATCH);
    attn_kernel<<<grid, 128, 98304>>>(x, Wq, k, v, out);
}